// round 11
// baseline (speedup 1.0000x reference)
#include <cuda_runtime.h>
#include <cuda_fp16.h>
#include <cuda_bf16.h>
#include <cstdint>

#define MAXN 100000
#define MAXE 3200000
#define INF  256
#define OUTF 64
#define ALPHA 0.2f

// Static scratch
__device__ __half g_hh[(size_t)MAXN * OUTF];  // 12.8 MB (fp16 h for gather)
__device__ float  g_s1[MAXN];
__device__ float  g_s2[MAXN];
__device__ float  g_den[MAXN];
__device__ int    g_deg[MAXN];
__device__ int    g_ptr[MAXN];
__device__ int    g_cur[MAXN];
__device__ int    g_bsum[128];
__device__ int2   g_pack[MAXE];               // (dst, exp(e)) grouped by src
__device__ uint4  g_wp[16 * 64 * 4];          // W fragment-packed
__device__ int    g_is64;

// ---------------------------------------------------------------------------
__global__ void k_detect(const int* __restrict__ adj32, int E) {
    __shared__ int sh[256];
    int t = threadIdx.x;
    int acc = 0;
#pragma unroll
    for (int j = 0; j < 4; j++) {
        int idx = 2 * (t * 4 + j) + 1;
        if (idx < 2 * E) acc |= adj32[idx];
    }
    sh[t] = acc;
    __syncthreads();
    for (int s = 128; s; s >>= 1) {
        if (t < s) sh[t] |= sh[t + s];
        __syncthreads();
    }
    if (t == 0) g_is64 = (sh[0] == 0) ? 1 : 0;
}

// Pack W into mma-fragment order with bf16 hi/lo split.
__global__ void k_wt(const float* __restrict__ W) {
    int i = blockIdx.x * blockDim.x + threadIdx.x;
    if (i >= 16 * 64 * 4) return;
    int tig = i & 3;
    int o   = (i >> 2) & 63;
    int ks  = i >> 8;
    int k0  = ks * 16 + 2 * tig;
    float w0 = W[o * INF + k0],     w1 = W[o * INF + k0 + 1];
    float w8 = W[o * INF + k0 + 8], w9 = W[o * INF + k0 + 9];
    __nv_bfloat162 h01 = __floats2bfloat162_rn(w0, w1);
    __nv_bfloat162 h89 = __floats2bfloat162_rn(w8, w9);
    __nv_bfloat162 l01 = __floats2bfloat162_rn(w0 - __bfloat162float(h01.x),
                                               w1 - __bfloat162float(h01.y));
    __nv_bfloat162 l89 = __floats2bfloat162_rn(w8 - __bfloat162float(h89.x),
                                               w9 - __bfloat162float(h89.y));
    uint4 u;
    u.x = *(unsigned*)&h01; u.y = *(unsigned*)&h89;
    u.z = *(unsigned*)&l01; u.w = *(unsigned*)&l89;
    g_wp[i] = u;
}

__global__ void k_init(int N) {
    int i = blockIdx.x * blockDim.x + threadIdx.x;
    if (i < N) { g_den[i] = 0.0f; g_deg[i] = 0; }
}

// ---------------------------------------------------------------------------
// Tensor-core GEMM, zero-smem (R8 measured-best version).
// ---------------------------------------------------------------------------
__device__ __forceinline__ void mma_bf16(float* d, const uint32_t* a,
                                         uint32_t b0, uint32_t b1) {
    asm volatile(
        "mma.sync.aligned.m16n8k16.row.col.f32.bf16.bf16.f32 "
        "{%0,%1,%2,%3}, {%4,%5,%6,%7}, {%8,%9}, {%0,%1,%2,%3};"
        : "+f"(d[0]), "+f"(d[1]), "+f"(d[2]), "+f"(d[3])
        : "r"(a[0]), "r"(a[1]), "r"(a[2]), "r"(a[3]), "r"(b0), "r"(b1));
}

__device__ __forceinline__ uint32_t pack_hi(float2 v, float2* res) {
    __nv_bfloat162 h = __floats2bfloat162_rn(v.x, v.y);
    res->x = v.x - __bfloat162float(h.x);
    res->y = v.y - __bfloat162float(h.y);
    return *(unsigned*)&h;
}
__device__ __forceinline__ uint32_t pack_lo(float2 r) {
    __nv_bfloat162 l = __floats2bfloat162_rn(r.x, r.y);
    return *(unsigned*)&l;
}

__global__ void __launch_bounds__(256) k_gemm(
    const float* __restrict__ x, const float* __restrict__ b,
    const float* __restrict__ a, int N)
{
    int t    = threadIdx.x;
    int warp = t >> 5;
    int lane = t & 31;
    int g    = lane >> 2;
    int tig  = lane & 3;
    int base = blockIdx.x * 128;
    int m0   = warp * 16;

    int node0 = base + m0 + g;
    int node1 = node0 + 8;
    bool v0 = node0 < N, v1 = node1 < N;
    const float2* x0 = (const float2*)(x + (size_t)node0 * INF);
    const float2* x1 = (const float2*)(x + (size_t)node1 * INF);

    float d[8][4];
#pragma unroll
    for (int n = 0; n < 8; n++)
#pragma unroll
        for (int i = 0; i < 4; i++) d[n][i] = 0.f;

    const float2 z2 = make_float2(0.f, 0.f);

#pragma unroll 4
    for (int ks = 0; ks < 16; ks++) {
        float2 w00 = v0 ? __ldg(x0 + ks * 8 + tig)     : z2;
        float2 w01 = v0 ? __ldg(x0 + ks * 8 + tig + 4) : z2;
        float2 w10 = v1 ? __ldg(x1 + ks * 8 + tig)     : z2;
        float2 w11 = v1 ? __ldg(x1 + ks * 8 + tig + 4) : z2;

        uint32_t a_hi[4], a_lo[4];
        float2 r;
        a_hi[0] = pack_hi(w00, &r); a_lo[0] = pack_lo(r);
        a_hi[1] = pack_hi(w10, &r); a_lo[1] = pack_lo(r);
        a_hi[2] = pack_hi(w01, &r); a_lo[2] = pack_lo(r);
        a_hi[3] = pack_hi(w11, &r); a_lo[3] = pack_lo(r);

        const uint4* wrow = g_wp + (ks * 64 + g) * 4 + tig;
#pragma unroll
        for (int n = 0; n < 8; n++) {
            uint4 wv = __ldg(wrow + n * 32);
            mma_bf16(d[n], a_hi, wv.x, wv.y);
            mma_bf16(d[n], a_hi, wv.z, wv.w);
            mma_bf16(d[n], a_lo, wv.x, wv.y);
        }
    }

    float p1a = 0.f, p2a = 0.f, p1b = 0.f, p2b = 0.f;
#pragma unroll
    for (int n = 0; n < 8; n++) {
        int o0 = n * 8 + tig * 2;
        float bb0 = __ldg(b + o0), bb1 = __ldg(b + o0 + 1);
        float h0 = d[n][0] + bb0, h1 = d[n][1] + bb1;
        float h2 = d[n][2] + bb0, h3 = d[n][3] + bb1;
        if (v0)
            *(__half2*)(g_hh + (size_t)node0 * OUTF + o0) = __floats2half2_rn(h0, h1);
        if (v1)
            *(__half2*)(g_hh + (size_t)node1 * OUTF + o0) = __floats2half2_rn(h2, h3);
        float a10 = __ldg(a + o0), a11 = __ldg(a + o0 + 1);
        float a20 = __ldg(a + OUTF + o0), a21 = __ldg(a + OUTF + o0 + 1);
        p1a += h0 * a10 + h1 * a11;
        p2a += h0 * a20 + h1 * a21;
        p1b += h2 * a10 + h3 * a11;
        p2b += h2 * a20 + h3 * a21;
    }
#pragma unroll
    for (int off = 1; off <= 2; off <<= 1) {
        p1a += __shfl_xor_sync(0xffffffffu, p1a, off);
        p2a += __shfl_xor_sync(0xffffffffu, p2a, off);
        p1b += __shfl_xor_sync(0xffffffffu, p1b, off);
        p2b += __shfl_xor_sync(0xffffffffu, p2b, off);
    }
    if (tig == 0) {
        if (v0) { g_s1[node0] = p1a; g_s2[node0] = p2a; }
        if (v1) { g_s1[node1] = p1b; g_s2[node1] = p2b; }
    }
}

// ---------------------------------------------------------------------------
// Degree histogram, 2 edges per thread via one 16B load (int64 src words).
// ---------------------------------------------------------------------------
__global__ void k_hist(const void* __restrict__ adj, int E) {
    int i = blockIdx.x * blockDim.x + threadIdx.x;   // pair index
    int e0 = 2 * i;
    if (e0 >= E) return;
    int e1 = e0 + 1;
    if (g_is64) {
        int4 v = __ldg((const int4*)adj + i);        // src[e0] lo/hi, src[e1] lo/hi
        atomicAdd(&g_deg[v.x], 1);
        if (e1 < E) atomicAdd(&g_deg[v.z], 1);
    } else {
        int2 v = __ldg((const int2*)adj + i);
        atomicAdd(&g_deg[v.x], 1);
        if (e1 < E) atomicAdd(&g_deg[v.y], 1);
    }
}

__global__ void k_scanA(int N) {
    __shared__ int sh[1024];
    int i = blockIdx.x * 1024 + threadIdx.x;
    int v = (i < N) ? g_deg[i] : 0;
    sh[threadIdx.x] = v;
    __syncthreads();
#pragma unroll
    for (int off = 1; off < 1024; off <<= 1) {
        int add = (threadIdx.x >= off) ? sh[threadIdx.x - off] : 0;
        __syncthreads();
        sh[threadIdx.x] += add;
        __syncthreads();
    }
    if (i < N) g_ptr[i] = sh[threadIdx.x] - v;
    if (threadIdx.x == 1023) g_bsum[blockIdx.x] = sh[1023];
}

__global__ void k_scanB(int nb) {
    __shared__ int sh[128];
    int t = threadIdx.x;
    int v = (t < nb) ? g_bsum[t] : 0;
    sh[t] = v;
    __syncthreads();
#pragma unroll
    for (int off = 1; off < 128; off <<= 1) {
        int add = (t >= off) ? sh[t - off] : 0;
        __syncthreads();
        sh[t] += add;
        __syncthreads();
    }
    if (t < nb) g_bsum[t] = sh[t] - v;
}

__global__ void k_scanC(int N) {
    int i = blockIdx.x * blockDim.x + threadIdx.x;
    if (i < N) {
        int p = g_ptr[i] + g_bsum[i >> 10];
        g_ptr[i] = p;
        g_cur[i] = p;
    }
}

// ---------------------------------------------------------------------------
__global__ void k_edge12(const void* __restrict__ adj, int E) {
    int i = blockIdx.x * blockDim.x + threadIdx.x;
    if (i >= E) return;
    int s, d;
    if (g_is64) {
        const int* a = (const int*)adj;
        s = a[2 * (size_t)i];
        d = a[2 * ((size_t)i + E)];
    } else {
        const int* a = (const int*)adj;
        s = a[i];
        d = a[(size_t)i + E];
    }
    float e = g_s1[s] + g_s2[d];
    e = e > 0.f ? e : ALPHA * e;
    float ex = __expf(e);
    atomicAdd(&g_den[d], ex);
    int pos = atomicAdd(&g_cur[s], 1);
    g_pack[pos] = make_int2(d, __float_as_int(ex));
}

// ---------------------------------------------------------------------------
// CSR aggregation: 16 lanes/node, 4-edge-wide body with 4-pack prefetch.
// Tail handled by clamped (always-valid) indices + zeroed att.
// ---------------------------------------------------------------------------
__global__ void __launch_bounds__(256) k_edge3(float* __restrict__ out, int N) {
    int t = threadIdx.x;
    int node = blockIdx.x * 16 + (t >> 4);
    int lane = t & 15;
    if (node >= N) return;
    int start = g_ptr[node];
    int deg   = g_deg[node];
    int last  = start + deg - 1;
    float4 acc = make_float4(0.f, 0.f, 0.f, 0.f);

    if (deg > 0) {
        int2 p0 = __ldg(&g_pack[start]);
        int2 p1 = __ldg(&g_pack[min(start + 1, last)]);
        int2 p2 = __ldg(&g_pack[min(start + 2, last)]);
        int2 p3 = __ldg(&g_pack[min(start + 3, last)]);
        for (int j = 0; j < deg; j += 4) {
            // prefetch next group (clamped; always valid)
            int nb = start + j + 4;
            int2 q0 = __ldg(&g_pack[min(nb,     last)]);
            int2 q1 = __ldg(&g_pack[min(nb + 1, last)]);
            int2 q2 = __ldg(&g_pack[min(nb + 2, last)]);
            int2 q3 = __ldg(&g_pack[min(nb + 3, last)]);

            float dn0 = __ldg(&g_den[p0.x]);
            float dn1 = __ldg(&g_den[p1.x]);
            float dn2 = __ldg(&g_den[p2.x]);
            float dn3 = __ldg(&g_den[p3.x]);
            uint2 u0 = __ldg((const uint2*)(g_hh + (size_t)p0.x * OUTF) + lane);
            uint2 u1 = __ldg((const uint2*)(g_hh + (size_t)p1.x * OUTF) + lane);
            uint2 u2 = __ldg((const uint2*)(g_hh + (size_t)p2.x * OUTF) + lane);
            uint2 u3 = __ldg((const uint2*)(g_hh + (size_t)p3.x * OUTF) + lane);

            float att0 = __fdividef(__int_as_float(p0.y), dn0);
            float att1 = (j + 1 < deg) ? __fdividef(__int_as_float(p1.y), dn1) : 0.f;
            float att2 = (j + 2 < deg) ? __fdividef(__int_as_float(p2.y), dn2) : 0.f;
            float att3 = (j + 3 < deg) ? __fdividef(__int_as_float(p3.y), dn3) : 0.f;

            float2 f;
            f = __half22float2(*(__half2*)&u0.x); acc.x += att0 * f.x; acc.y += att0 * f.y;
            f = __half22float2(*(__half2*)&u0.y); acc.z += att0 * f.x; acc.w += att0 * f.y;
            f = __half22float2(*(__half2*)&u1.x); acc.x += att1 * f.x; acc.y += att1 * f.y;
            f = __half22float2(*(__half2*)&u1.y); acc.z += att1 * f.x; acc.w += att1 * f.y;
            f = __half22float2(*(__half2*)&u2.x); acc.x += att2 * f.x; acc.y += att2 * f.y;
            f = __half22float2(*(__half2*)&u2.y); acc.z += att2 * f.x; acc.w += att2 * f.y;
            f = __half22float2(*(__half2*)&u3.x); acc.x += att3 * f.x; acc.y += att3 * f.y;
            f = __half22float2(*(__half2*)&u3.y); acc.z += att3 * f.x; acc.w += att3 * f.y;

            p0 = q0; p1 = q1; p2 = q2; p3 = q3;
        }
    }
    acc.x = acc.x > 0.f ? acc.x : expm1f(acc.x);
    acc.y = acc.y > 0.f ? acc.y : expm1f(acc.y);
    acc.z = acc.z > 0.f ? acc.z : expm1f(acc.z);
    acc.w = acc.w > 0.f ? acc.w : expm1f(acc.w);
    *((float4*)(out + (size_t)node * OUTF) + lane) = acc;
}

extern "C" void kernel_launch(void* const* d_in, const int* in_sizes, int n_in,
                              void* d_out, int out_size)
{
    const void*  adj = d_in[0];
    const float* x   = (const float*)d_in[1];
    const float* W   = (const float*)d_in[2];
    const float* b   = (const float*)d_in[3];
    const float* a   = (const float*)d_in[4];
    float* out = (float*)d_out;

    int E = in_sizes[0] / 2;
    int N = in_sizes[1] / INF;
    int nScanBlocks = (N + 1023) / 1024;
    int nPairs = (E + 1) / 2;

    k_detect<<<1, 256>>>((const int*)adj, E);
    k_wt<<<16, 256>>>(W);
    k_init<<<(N + 255) / 256, 256>>>(N);
    k_gemm<<<(N + 127) / 128, 256>>>(x, b, a, N);   // slot 4: profiled control
    k_hist<<<(nPairs + 255) / 256, 256>>>(adj, E);
    k_scanA<<<nScanBlocks, 1024>>>(N);
    k_scanB<<<1, 128>>>(nScanBlocks);
    k_scanC<<<(N + 255) / 256, 256>>>(N);
    k_edge12<<<(E + 255) / 256, 256>>>(adj, E);
    k_edge3<<<(N + 15) / 16, 256>>>(out, N);
}

// round 12
// speedup vs baseline: 1.0119x; 1.0119x over previous
#include <cuda_runtime.h>
#include <cuda_fp16.h>
#include <cuda_bf16.h>
#include <cstdint>

#define MAXN 100000
#define MAXE 3200000
#define INF  256
#define OUTF 64
#define ALPHA 0.2f

// Static scratch
__device__ __half g_hh[(size_t)MAXN * OUTF];  // 12.8 MB (fp16 h for gather)
__device__ float  g_s1[MAXN];
__device__ float  g_s2[MAXN];
__device__ float  g_den[MAXN];
__device__ int    g_deg[MAXN];
__device__ int    g_ptr[MAXN];
__device__ int    g_cur[MAXN];
__device__ int    g_bsum[128];
__device__ int2   g_pack[MAXE];               // (dst, exp(e)) grouped by src
__device__ uint4  g_wp[16 * 64 * 4];          // W fragment-packed
__device__ int    g_is64;

// ---------------------------------------------------------------------------
__global__ void k_detect(const int* __restrict__ adj32, int E) {
    __shared__ int sh[256];
    int t = threadIdx.x;
    int acc = 0;
#pragma unroll
    for (int j = 0; j < 4; j++) {
        int idx = 2 * (t * 4 + j) + 1;
        if (idx < 2 * E) acc |= adj32[idx];
    }
    sh[t] = acc;
    __syncthreads();
    for (int s = 128; s; s >>= 1) {
        if (t < s) sh[t] |= sh[t + s];
        __syncthreads();
    }
    if (t == 0) g_is64 = (sh[0] == 0) ? 1 : 0;
}

// Pack W into mma-fragment order with bf16 hi/lo split.
__global__ void k_wt(const float* __restrict__ W) {
    int i = blockIdx.x * blockDim.x + threadIdx.x;
    if (i >= 16 * 64 * 4) return;
    int tig = i & 3;
    int o   = (i >> 2) & 63;
    int ks  = i >> 8;
    int k0  = ks * 16 + 2 * tig;
    float w0 = W[o * INF + k0],     w1 = W[o * INF + k0 + 1];
    float w8 = W[o * INF + k0 + 8], w9 = W[o * INF + k0 + 9];
    __nv_bfloat162 h01 = __floats2bfloat162_rn(w0, w1);
    __nv_bfloat162 h89 = __floats2bfloat162_rn(w8, w9);
    __nv_bfloat162 l01 = __floats2bfloat162_rn(w0 - __bfloat162float(h01.x),
                                               w1 - __bfloat162float(h01.y));
    __nv_bfloat162 l89 = __floats2bfloat162_rn(w8 - __bfloat162float(h89.x),
                                               w9 - __bfloat162float(h89.y));
    uint4 u;
    u.x = *(unsigned*)&h01; u.y = *(unsigned*)&h89;
    u.z = *(unsigned*)&l01; u.w = *(unsigned*)&l89;
    g_wp[i] = u;
}

__global__ void k_init(int N) {
    int i = blockIdx.x * blockDim.x + threadIdx.x;
    if (i < N) { g_den[i] = 0.0f; g_deg[i] = 0; }
}

// ---------------------------------------------------------------------------
// Tensor-core GEMM, zero-smem. Single change this round: min 4 blocks/SM.
// ---------------------------------------------------------------------------
__device__ __forceinline__ void mma_bf16(float* d, const uint32_t* a,
                                         uint32_t b0, uint32_t b1) {
    asm volatile(
        "mma.sync.aligned.m16n8k16.row.col.f32.bf16.bf16.f32 "
        "{%0,%1,%2,%3}, {%4,%5,%6,%7}, {%8,%9}, {%0,%1,%2,%3};"
        : "+f"(d[0]), "+f"(d[1]), "+f"(d[2]), "+f"(d[3])
        : "r"(a[0]), "r"(a[1]), "r"(a[2]), "r"(a[3]), "r"(b0), "r"(b1));
}

__device__ __forceinline__ uint32_t pack_hi(float2 v, float2* res) {
    __nv_bfloat162 h = __floats2bfloat162_rn(v.x, v.y);
    res->x = v.x - __bfloat162float(h.x);
    res->y = v.y - __bfloat162float(h.y);
    return *(unsigned*)&h;
}
__device__ __forceinline__ uint32_t pack_lo(float2 r) {
    __nv_bfloat162 l = __floats2bfloat162_rn(r.x, r.y);
    return *(unsigned*)&l;
}

__global__ void __launch_bounds__(256, 4) k_gemm(
    const float* __restrict__ x, const float* __restrict__ b,
    const float* __restrict__ a, int N)
{
    int t    = threadIdx.x;
    int warp = t >> 5;
    int lane = t & 31;
    int g    = lane >> 2;
    int tig  = lane & 3;
    int base = blockIdx.x * 128;
    int m0   = warp * 16;

    int node0 = base + m0 + g;
    int node1 = node0 + 8;
    bool v0 = node0 < N, v1 = node1 < N;
    const float2* x0 = (const float2*)(x + (size_t)node0 * INF);
    const float2* x1 = (const float2*)(x + (size_t)node1 * INF);

    float d[8][4];
#pragma unroll
    for (int n = 0; n < 8; n++)
#pragma unroll
        for (int i = 0; i < 4; i++) d[n][i] = 0.f;

    const float2 z2 = make_float2(0.f, 0.f);

#pragma unroll 4
    for (int ks = 0; ks < 16; ks++) {
        float2 w00 = v0 ? __ldg(x0 + ks * 8 + tig)     : z2;
        float2 w01 = v0 ? __ldg(x0 + ks * 8 + tig + 4) : z2;
        float2 w10 = v1 ? __ldg(x1 + ks * 8 + tig)     : z2;
        float2 w11 = v1 ? __ldg(x1 + ks * 8 + tig + 4) : z2;

        uint32_t a_hi[4], a_lo[4];
        float2 r;
        a_hi[0] = pack_hi(w00, &r); a_lo[0] = pack_lo(r);
        a_hi[1] = pack_hi(w10, &r); a_lo[1] = pack_lo(r);
        a_hi[2] = pack_hi(w01, &r); a_lo[2] = pack_lo(r);
        a_hi[3] = pack_hi(w11, &r); a_lo[3] = pack_lo(r);

        const uint4* wrow = g_wp + (ks * 64 + g) * 4 + tig;
#pragma unroll
        for (int n = 0; n < 8; n++) {
            uint4 wv = __ldg(wrow + n * 32);
            mma_bf16(d[n], a_hi, wv.x, wv.y);
            mma_bf16(d[n], a_hi, wv.z, wv.w);
            mma_bf16(d[n], a_lo, wv.x, wv.y);
        }
    }

    float p1a = 0.f, p2a = 0.f, p1b = 0.f, p2b = 0.f;
#pragma unroll
    for (int n = 0; n < 8; n++) {
        int o0 = n * 8 + tig * 2;
        float bb0 = __ldg(b + o0), bb1 = __ldg(b + o0 + 1);
        float h0 = d[n][0] + bb0, h1 = d[n][1] + bb1;
        float h2 = d[n][2] + bb0, h3 = d[n][3] + bb1;
        if (v0)
            *(__half2*)(g_hh + (size_t)node0 * OUTF + o0) = __floats2half2_rn(h0, h1);
        if (v1)
            *(__half2*)(g_hh + (size_t)node1 * OUTF + o0) = __floats2half2_rn(h2, h3);
        float a10 = __ldg(a + o0), a11 = __ldg(a + o0 + 1);
        float a20 = __ldg(a + OUTF + o0), a21 = __ldg(a + OUTF + o0 + 1);
        p1a += h0 * a10 + h1 * a11;
        p2a += h0 * a20 + h1 * a21;
        p1b += h2 * a10 + h3 * a11;
        p2b += h2 * a20 + h3 * a21;
    }
#pragma unroll
    for (int off = 1; off <= 2; off <<= 1) {
        p1a += __shfl_xor_sync(0xffffffffu, p1a, off);
        p2a += __shfl_xor_sync(0xffffffffu, p2a, off);
        p1b += __shfl_xor_sync(0xffffffffu, p1b, off);
        p2b += __shfl_xor_sync(0xffffffffu, p2b, off);
    }
    if (tig == 0) {
        if (v0) { g_s1[node0] = p1a; g_s2[node0] = p2a; }
        if (v1) { g_s1[node1] = p1b; g_s2[node1] = p2b; }
    }
}

// ---------------------------------------------------------------------------
__global__ void k_hist(const void* __restrict__ adj, int E) {
    int i = blockIdx.x * blockDim.x + threadIdx.x;
    if (i >= E) return;
    int s = g_is64 ? ((const int*)adj)[2 * (size_t)i] : ((const int*)adj)[i];
    atomicAdd(&g_deg[s], 1);
}

__global__ void k_scanA(int N) {
    __shared__ int sh[1024];
    int i = blockIdx.x * 1024 + threadIdx.x;
    int v = (i < N) ? g_deg[i] : 0;
    sh[threadIdx.x] = v;
    __syncthreads();
#pragma unroll
    for (int off = 1; off < 1024; off <<= 1) {
        int add = (threadIdx.x >= off) ? sh[threadIdx.x - off] : 0;
        __syncthreads();
        sh[threadIdx.x] += add;
        __syncthreads();
    }
    if (i < N) g_ptr[i] = sh[threadIdx.x] - v;
    if (threadIdx.x == 1023) g_bsum[blockIdx.x] = sh[1023];
}

__global__ void k_scanB(int nb) {
    __shared__ int sh[128];
    int t = threadIdx.x;
    int v = (t < nb) ? g_bsum[t] : 0;
    sh[t] = v;
    __syncthreads();
#pragma unroll
    for (int off = 1; off < 128; off <<= 1) {
        int add = (t >= off) ? sh[t - off] : 0;
        __syncthreads();
        sh[t] += add;
        __syncthreads();
    }
    if (t < nb) g_bsum[t] = sh[t] - v;
}

__global__ void k_scanC(int N) {
    int i = blockIdx.x * blockDim.x + threadIdx.x;
    if (i < N) {
        int p = g_ptr[i] + g_bsum[i >> 10];
        g_ptr[i] = p;
        g_cur[i] = p;
    }
}

// ---------------------------------------------------------------------------
__global__ void k_edge12(const void* __restrict__ adj, int E) {
    int i = blockIdx.x * blockDim.x + threadIdx.x;
    if (i >= E) return;
    int s, d;
    if (g_is64) {
        const int* a = (const int*)adj;
        s = a[2 * (size_t)i];
        d = a[2 * ((size_t)i + E)];
    } else {
        const int* a = (const int*)adj;
        s = a[i];
        d = a[(size_t)i + E];
    }
    float e = g_s1[s] + g_s2[d];
    e = e > 0.f ? e : ALPHA * e;
    float ex = __expf(e);
    atomicAdd(&g_den[d], ex);
    int pos = atomicAdd(&g_cur[s], 1);
    g_pack[pos] = make_int2(d, __float_as_int(ex));
}

// ---------------------------------------------------------------------------
// CSR aggregation with fp16 h gather: 16 lanes/node, 1-ahead pack prefetch.
// (Measured-best variant; do not widen — R8-R10 showed regressions.)
// ---------------------------------------------------------------------------
__global__ void __launch_bounds__(256) k_edge3(float* __restrict__ out, int N) {
    int t = threadIdx.x;
    int node = blockIdx.x * 16 + (t >> 4);
    int lane = t & 15;
    if (node >= N) return;
    int start = g_ptr[node];
    int deg   = g_deg[node];
    float4 acc = make_float4(0.f, 0.f, 0.f, 0.f);
    if (deg > 0) {
        int2 p = __ldg(&g_pack[start]);
        for (int j = 0; j < deg - 1; j++) {
            int2 pn = __ldg(&g_pack[start + j + 1]);
            int d = p.x;
            float att = __fdividef(__int_as_float(p.y), __ldg(&g_den[d]));
            uint2 u = __ldg((const uint2*)(g_hh + (size_t)d * OUTF) + lane);
            float2 f0 = __half22float2(*(__half2*)&u.x);
            float2 f1 = __half22float2(*(__half2*)&u.y);
            acc.x += att * f0.x; acc.y += att * f0.y;
            acc.z += att * f1.x; acc.w += att * f1.y;
            p = pn;
        }
        int d = p.x;
        float att = __fdividef(__int_as_float(p.y), __ldg(&g_den[d]));
        uint2 u = __ldg((const uint2*)(g_hh + (size_t)d * OUTF) + lane);
        float2 f0 = __half22float2(*(__half2*)&u.x);
        float2 f1 = __half22float2(*(__half2*)&u.y);
        acc.x += att * f0.x; acc.y += att * f0.y;
        acc.z += att * f1.x; acc.w += att * f1.y;
    }
    acc.x = acc.x > 0.f ? acc.x : expm1f(acc.x);
    acc.y = acc.y > 0.f ? acc.y : expm1f(acc.y);
    acc.z = acc.z > 0.f ? acc.z : expm1f(acc.z);
    acc.w = acc.w > 0.f ? acc.w : expm1f(acc.w);
    *((float4*)(out + (size_t)node * OUTF) + lane) = acc;
}

extern "C" void kernel_launch(void* const* d_in, const int* in_sizes, int n_in,
                              void* d_out, int out_size)
{
    const void*  adj = d_in[0];
    const float* x   = (const float*)d_in[1];
    const float* W   = (const float*)d_in[2];
    const float* b   = (const float*)d_in[3];
    const float* a   = (const float*)d_in[4];
    float* out = (float*)d_out;

    int E = in_sizes[0] / 2;
    int N = in_sizes[1] / INF;
    int nScanBlocks = (N + 1023) / 1024;

    k_detect<<<1, 256>>>((const int*)adj, E);
    k_wt<<<16, 256>>>(W);
    k_init<<<(N + 255) / 256, 256>>>(N);
    k_gemm<<<(N + 127) / 128, 256>>>(x, b, a, N);   // slot 4: profiled control
    k_hist<<<(E + 255) / 256, 256>>>(adj, E);
    k_scanA<<<nScanBlocks, 1024>>>(N);
    k_scanB<<<1, 128>>>(nScanBlocks);
    k_scanC<<<(N + 255) / 256, 256>>>(N);
    k_edge12<<<(E + 255) / 256, 256>>>(adj, E);
    k_edge3<<<(N + 15) / 16, 256>>>(out, N);
}

// round 13
// speedup vs baseline: 1.1300x; 1.1167x over previous
#include <cuda_runtime.h>
#include <cuda_fp16.h>
#include <cuda_bf16.h>
#include <cstdint>

#define MAXN 100000
#define MAXE 3200000
#define INF  256
#define OUTF 64
#define ALPHA 0.2f

// Static scratch
__device__ __half g_hh[(size_t)MAXN * OUTF];  // 12.8 MB (fp16 h for gather)
__device__ float  g_s1[MAXN];
__device__ float  g_s2[MAXN];
__device__ float  g_den[MAXN];
__device__ int    g_deg[MAXN];
__device__ int    g_ptr[MAXN];
__device__ int    g_cur[MAXN];
__device__ int    g_bsum[128];
__device__ int2   g_pack[MAXE];               // (dst, exp(e)) grouped by src
__device__ uint4  g_wp[16 * 64 * 4];          // W fragment-packed
__device__ int    g_is64;

// ---------------------------------------------------------------------------
__global__ void k_detect(const int* __restrict__ adj32, int E) {
    __shared__ int sh[256];
    int t = threadIdx.x;
    int acc = 0;
#pragma unroll
    for (int j = 0; j < 4; j++) {
        int idx = 2 * (t * 4 + j) + 1;
        if (idx < 2 * E) acc |= adj32[idx];
    }
    sh[t] = acc;
    __syncthreads();
    for (int s = 128; s; s >>= 1) {
        if (t < s) sh[t] |= sh[t + s];
        __syncthreads();
    }
    if (t == 0) g_is64 = (sh[0] == 0) ? 1 : 0;
}

// Pack W into mma-fragment order with bf16 hi/lo split.
__global__ void k_wt(const float* __restrict__ W) {
    int i = blockIdx.x * blockDim.x + threadIdx.x;
    if (i >= 16 * 64 * 4) return;
    int tig = i & 3;
    int o   = (i >> 2) & 63;
    int ks  = i >> 8;
    int k0  = ks * 16 + 2 * tig;
    float w0 = W[o * INF + k0],     w1 = W[o * INF + k0 + 1];
    float w8 = W[o * INF + k0 + 8], w9 = W[o * INF + k0 + 9];
    __nv_bfloat162 h01 = __floats2bfloat162_rn(w0, w1);
    __nv_bfloat162 h89 = __floats2bfloat162_rn(w8, w9);
    __nv_bfloat162 l01 = __floats2bfloat162_rn(w0 - __bfloat162float(h01.x),
                                               w1 - __bfloat162float(h01.y));
    __nv_bfloat162 l89 = __floats2bfloat162_rn(w8 - __bfloat162float(h89.x),
                                               w9 - __bfloat162float(h89.y));
    uint4 u;
    u.x = *(unsigned*)&h01; u.y = *(unsigned*)&h89;
    u.z = *(unsigned*)&l01; u.w = *(unsigned*)&l89;
    g_wp[i] = u;
}

__global__ void k_init(int N) {
    int i = blockIdx.x * blockDim.x + threadIdx.x;
    if (i < N) { g_den[i] = 0.0f; g_deg[i] = 0; }
}

// ---------------------------------------------------------------------------
// Tensor-core GEMM, zero-smem (R7 measured-best: 76 regs, occ 33%).
// ---------------------------------------------------------------------------
__device__ __forceinline__ void mma_bf16(float* d, const uint32_t* a,
                                         uint32_t b0, uint32_t b1) {
    asm volatile(
        "mma.sync.aligned.m16n8k16.row.col.f32.bf16.bf16.f32 "
        "{%0,%1,%2,%3}, {%4,%5,%6,%7}, {%8,%9}, {%0,%1,%2,%3};"
        : "+f"(d[0]), "+f"(d[1]), "+f"(d[2]), "+f"(d[3])
        : "r"(a[0]), "r"(a[1]), "r"(a[2]), "r"(a[3]), "r"(b0), "r"(b1));
}

__device__ __forceinline__ uint32_t pack_hi(float2 v, float2* res) {
    __nv_bfloat162 h = __floats2bfloat162_rn(v.x, v.y);
    res->x = v.x - __bfloat162float(h.x);
    res->y = v.y - __bfloat162float(h.y);
    return *(unsigned*)&h;
}
__device__ __forceinline__ uint32_t pack_lo(float2 r) {
    __nv_bfloat162 l = __floats2bfloat162_rn(r.x, r.y);
    return *(unsigned*)&l;
}

__global__ void __launch_bounds__(256) k_gemm(
    const float* __restrict__ x, const float* __restrict__ b,
    const float* __restrict__ a, int N)
{
    int t    = threadIdx.x;
    int warp = t >> 5;
    int lane = t & 31;
    int g    = lane >> 2;
    int tig  = lane & 3;
    int base = blockIdx.x * 128;
    int m0   = warp * 16;

    int node0 = base + m0 + g;
    int node1 = node0 + 8;
    bool v0 = node0 < N, v1 = node1 < N;
    const float2* x0 = (const float2*)(x + (size_t)node0 * INF);
    const float2* x1 = (const float2*)(x + (size_t)node1 * INF);

    float d[8][4];
#pragma unroll
    for (int n = 0; n < 8; n++)
#pragma unroll
        for (int i = 0; i < 4; i++) d[n][i] = 0.f;

    const float2 z2 = make_float2(0.f, 0.f);

#pragma unroll 4
    for (int ks = 0; ks < 16; ks++) {
        float2 w00 = v0 ? __ldg(x0 + ks * 8 + tig)     : z2;
        float2 w01 = v0 ? __ldg(x0 + ks * 8 + tig + 4) : z2;
        float2 w10 = v1 ? __ldg(x1 + ks * 8 + tig)     : z2;
        float2 w11 = v1 ? __ldg(x1 + ks * 8 + tig + 4) : z2;

        uint32_t a_hi[4], a_lo[4];
        float2 r;
        a_hi[0] = pack_hi(w00, &r); a_lo[0] = pack_lo(r);
        a_hi[1] = pack_hi(w10, &r); a_lo[1] = pack_lo(r);
        a_hi[2] = pack_hi(w01, &r); a_lo[2] = pack_lo(r);
        a_hi[3] = pack_hi(w11, &r); a_lo[3] = pack_lo(r);

        const uint4* wrow = g_wp + (ks * 64 + g) * 4 + tig;
#pragma unroll
        for (int n = 0; n < 8; n++) {
            uint4 wv = __ldg(wrow + n * 32);
            mma_bf16(d[n], a_hi, wv.x, wv.y);
            mma_bf16(d[n], a_hi, wv.z, wv.w);
            mma_bf16(d[n], a_lo, wv.x, wv.y);
        }
    }

    float p1a = 0.f, p2a = 0.f, p1b = 0.f, p2b = 0.f;
#pragma unroll
    for (int n = 0; n < 8; n++) {
        int o0 = n * 8 + tig * 2;
        float bb0 = __ldg(b + o0), bb1 = __ldg(b + o0 + 1);
        float h0 = d[n][0] + bb0, h1 = d[n][1] + bb1;
        float h2 = d[n][2] + bb0, h3 = d[n][3] + bb1;
        if (v0)
            *(__half2*)(g_hh + (size_t)node0 * OUTF + o0) = __floats2half2_rn(h0, h1);
        if (v1)
            *(__half2*)(g_hh + (size_t)node1 * OUTF + o0) = __floats2half2_rn(h2, h3);
        float a10 = __ldg(a + o0), a11 = __ldg(a + o0 + 1);
        float a20 = __ldg(a + OUTF + o0), a21 = __ldg(a + OUTF + o0 + 1);
        p1a += h0 * a10 + h1 * a11;
        p2a += h0 * a20 + h1 * a21;
        p1b += h2 * a10 + h3 * a11;
        p2b += h2 * a20 + h3 * a21;
    }
#pragma unroll
    for (int off = 1; off <= 2; off <<= 1) {
        p1a += __shfl_xor_sync(0xffffffffu, p1a, off);
        p2a += __shfl_xor_sync(0xffffffffu, p2a, off);
        p1b += __shfl_xor_sync(0xffffffffu, p1b, off);
        p2b += __shfl_xor_sync(0xffffffffu, p2b, off);
    }
    if (tig == 0) {
        if (v0) { g_s1[node0] = p1a; g_s2[node0] = p2a; }
        if (v1) { g_s1[node1] = p1b; g_s2[node1] = p2b; }
    }
}

// ---------------------------------------------------------------------------
__global__ void k_hist(const void* __restrict__ adj, int E) {
    int i = blockIdx.x * blockDim.x + threadIdx.x;
    if (i >= E) return;
    int s = g_is64 ? ((const int*)adj)[2 * (size_t)i] : ((const int*)adj)[i];
    atomicAdd(&g_deg[s], 1);
}

__global__ void k_scanA(int N) {
    __shared__ int sh[1024];
    int i = blockIdx.x * 1024 + threadIdx.x;
    int v = (i < N) ? g_deg[i] : 0;
    sh[threadIdx.x] = v;
    __syncthreads();
#pragma unroll
    for (int off = 1; off < 1024; off <<= 1) {
        int add = (threadIdx.x >= off) ? sh[threadIdx.x - off] : 0;
        __syncthreads();
        sh[threadIdx.x] += add;
        __syncthreads();
    }
    if (i < N) g_ptr[i] = sh[threadIdx.x] - v;
    if (threadIdx.x == 1023) g_bsum[blockIdx.x] = sh[1023];
}

__global__ void k_scanB(int nb) {
    __shared__ int sh[128];
    int t = threadIdx.x;
    int v = (t < nb) ? g_bsum[t] : 0;
    sh[t] = v;
    __syncthreads();
#pragma unroll
    for (int off = 1; off < 128; off <<= 1) {
        int add = (t >= off) ? sh[t - off] : 0;
        __syncthreads();
        sh[t] += add;
        __syncthreads();
    }
    if (t < nb) g_bsum[t] = sh[t] - v;
}

__global__ void k_scanC(int N) {
    int i = blockIdx.x * blockDim.x + threadIdx.x;
    if (i < N) {
        int p = g_ptr[i] + g_bsum[i >> 10];
        g_ptr[i] = p;
        g_cur[i] = p;
    }
}

// ---------------------------------------------------------------------------
__global__ void k_edge12(const void* __restrict__ adj, int E) {
    int i = blockIdx.x * blockDim.x + threadIdx.x;
    if (i >= E) return;
    int s, d;
    if (g_is64) {
        const int* a = (const int*)adj;
        s = a[2 * (size_t)i];
        d = a[2 * ((size_t)i + E)];
    } else {
        const int* a = (const int*)adj;
        s = a[i];
        d = a[(size_t)i + E];
    }
    float e = g_s1[s] + g_s2[d];
    e = e > 0.f ? e : ALPHA * e;
    float ex = __expf(e);
    atomicAdd(&g_den[d], ex);
    int pos = atomicAdd(&g_cur[s], 1);
    g_pack[pos] = make_int2(d, __float_as_int(ex));
}

// ---------------------------------------------------------------------------
// CSR aggregation with fp16 h gather: 16 lanes/node, 1-ahead pack prefetch.
// (Measured-best variant; widenings regressed in R8-R11.)
// ---------------------------------------------------------------------------
__global__ void __launch_bounds__(256) k_edge3(float* __restrict__ out, int N) {
    int t = threadIdx.x;
    int node = blockIdx.x * 16 + (t >> 4);
    int lane = t & 15;
    if (node >= N) return;
    int start = g_ptr[node];
    int deg   = g_deg[node];
    float4 acc = make_float4(0.f, 0.f, 0.f, 0.f);
    if (deg > 0) {
        int2 p = __ldg(&g_pack[start]);
        for (int j = 0; j < deg - 1; j++) {
            int2 pn = __ldg(&g_pack[start + j + 1]);
            int d = p.x;
            float att = __fdividef(__int_as_float(p.y), __ldg(&g_den[d]));
            uint2 u = __ldg((const uint2*)(g_hh + (size_t)d * OUTF) + lane);
            float2 f0 = __half22float2(*(__half2*)&u.x);
            float2 f1 = __half22float2(*(__half2*)&u.y);
            acc.x += att * f0.x; acc.y += att * f0.y;
            acc.z += att * f1.x; acc.w += att * f1.y;
            p = pn;
        }
        int d = p.x;
        float att = __fdividef(__int_as_float(p.y), __ldg(&g_den[d]));
        uint2 u = __ldg((const uint2*)(g_hh + (size_t)d * OUTF) + lane);
        float2 f0 = __half22float2(*(__half2*)&u.x);
        float2 f1 = __half22float2(*(__half2*)&u.y);
        acc.x += att * f0.x; acc.y += att * f0.y;
        acc.z += att * f1.x; acc.w += att * f1.y;
    }
    acc.x = acc.x > 0.f ? acc.x : expm1f(acc.x);
    acc.y = acc.y > 0.f ? acc.y : expm1f(acc.y);
    acc.z = acc.z > 0.f ? acc.z : expm1f(acc.z);
    acc.w = acc.w > 0.f ? acc.w : expm1f(acc.w);
    *((float4*)(out + (size_t)node * OUTF) + lane) = acc;
}

// ---------------------------------------------------------------------------
// Launch: fork a second stream so the hist/scan chain overlaps the GEMM.
// DAG:  main: wt -> gemm ----------------------\
//       s2:   detect -> init -> hist -> scans --+--> edge12 -> edge3
// All stream/event ops are capture-legal (no allocation of device memory).
// ---------------------------------------------------------------------------
extern "C" void kernel_launch(void* const* d_in, const int* in_sizes, int n_in,
                              void* d_out, int out_size)
{
    const void*  adj = d_in[0];
    const float* x   = (const float*)d_in[1];
    const float* W   = (const float*)d_in[2];
    const float* b   = (const float*)d_in[3];
    const float* a   = (const float*)d_in[4];
    float* out = (float*)d_out;

    int E = in_sizes[0] / 2;
    int N = in_sizes[1] / INF;
    int nScanBlocks = (N + 1023) / 1024;

    cudaStream_t s2;
    cudaStreamCreateWithFlags(&s2, cudaStreamNonBlocking);
    cudaEvent_t eFork, eJoin;
    cudaEventCreateWithFlags(&eFork, cudaEventDisableTiming);
    cudaEventCreateWithFlags(&eJoin, cudaEventDisableTiming);

    // Fork s2 off the main (capture) stream.
    cudaEventRecord(eFork, 0);
    cudaStreamWaitEvent(s2, eFork, 0);

    // Interleave host-side submission so k_gemm remains the 4th kernel launch
    // (profiled control slot).
    k_wt<<<16, 256>>>(W);                                    // 1 (main)
    k_detect<<<1, 256, 0, s2>>>((const int*)adj, E);         // 2 (s2)
    k_init<<<(N + 255) / 256, 256, 0, s2>>>(N);              // 3 (s2)
    k_gemm<<<(N + 127) / 128, 256>>>(x, b, a, N);            // 4 (main, profiled)
    k_hist<<<(E + 255) / 256, 256, 0, s2>>>(adj, E);         // 5 (s2)
    k_scanA<<<nScanBlocks, 1024, 0, s2>>>(N);                // 6 (s2)
    k_scanB<<<1, 128, 0, s2>>>(nScanBlocks);                 // 7 (s2)
    k_scanC<<<(N + 255) / 256, 256, 0, s2>>>(N);             // 8 (s2)
    cudaEventRecord(eJoin, s2);

    // Join: edge kernels need both the GEMM outputs and the CSR pointers.
    cudaStreamWaitEvent(0, eJoin, 0);
    k_edge12<<<(E + 255) / 256, 256>>>(adj, E);              // 9 (main)
    k_edge3<<<(N + 15) / 16, 256>>>(out, N);                 // 10 (main)

    cudaEventDestroy(eFork);
    cudaEventDestroy(eJoin);
    cudaStreamDestroy(s2);
}